// round 12
// baseline (speedup 1.0000x reference)
#include <cuda_runtime.h>
#include <cstdint>

// CRF negative log-likelihood on GB300 (sm_103a).
// B=512, S=1024, T=32. Forward/backward split at m=(S-1)/2:
//   Z = sum_t alpha_t(m) * beta_t(m).
// ONE fused launch, grid=3B: [0,B) fwd chains, [B,2B) bwd chains, [2B,3B)
// gold-score blocks. R11: zero via cudaMemsetAsync (no kernel), combine folded
// into the fused kernel via per-sequence atomic ticket (second finisher of the
// fwd/bwd pair does the alpha.beta dot), BWD chain symmetrized to ONE FMA by
// carrying v = pe*beta as the broadcast value (pe folded into off-chain coeffs).
// Per-step chain (unchanged core): SMEM broadcast (STS+BAR@nw=1+8x LDS.128
// volatile), 16x FFMA2 with preloaded exp(trans), raw-prefetch (PF=8) converted
// at consumption, rescale every 4 steps off-chain.

#define FULLMASK 0xFFFFFFFFu

__device__ float g_vec[2][2048][32];   // [dir][seq][tag] boundary vectors
__device__ float g_C[2][2048];         // [dir][seq] log2 offsets
__device__ int   g_ticket[2048];       // per-seq arrival ticket (self-resetting)

__device__ __forceinline__ float ex2f(float x) {
    float r; asm("ex2.approx.ftz.f32 %0, %1;" : "=f"(r) : "f"(x)); return r;
}
__device__ __forceinline__ float lg2f(float x) {
    float r; asm("lg2.approx.ftz.f32 %0, %1;" : "=f"(r) : "f"(x)); return r;
}
__device__ __forceinline__ unsigned long long packf2(float lo, float hi) {
    unsigned long long d; asm("mov.b64 %0, {%1, %2};" : "=l"(d) : "f"(lo), "f"(hi)); return d;
}
__device__ __forceinline__ void unpackf2(unsigned long long d, float& lo, float& hi) {
    asm("mov.b64 {%0, %1}, %2;" : "=f"(lo), "=f"(hi) : "l"(d));
}
__device__ __forceinline__ unsigned long long fma2(unsigned long long a,
                                                   unsigned long long b,
                                                   unsigned long long c) {
    unsigned long long d;
    asm("fma.rn.f32x2 %0, %1, %2, %3;" : "=l"(d) : "l"(a), "l"(b), "l"(c));
    return d;
}
__device__ __forceinline__ unsigned long long add2(unsigned long long a,
                                                   unsigned long long b) {
    unsigned long long d;
    asm("add.rn.f32x2 %0, %1, %2;" : "=l"(d) : "l"(a), "l"(b));
    return d;
}

// dot of broadcast slab with this lane's matrix pairs: 8x LDS.128 + 16x FFMA2
__device__ __forceinline__ float matvec_dot(uint32_t off, const unsigned long long* M2) {
    unsigned long long acc0 = 0ull, acc1 = 0ull, acc2 = 0ull, acc3 = 0ull;
    #pragma unroll
    for (int jj = 0; jj < 4; jj++) {
        unsigned long long q0, q1, q2, q3;
        asm volatile("ld.shared.v2.u64 {%0, %1}, [%2];"
            : "=l"(q0), "=l"(q1) : "r"(off + 32u * jj) : "memory");
        asm volatile("ld.shared.v2.u64 {%0, %1}, [%2 + 16];"
            : "=l"(q2), "=l"(q3) : "r"(off + 32u * jj) : "memory");
        acc0 = fma2(q0, M2[4 * jj + 0], acc0);
        acc1 = fma2(q1, M2[4 * jj + 1], acc1);
        acc2 = fma2(q2, M2[4 * jj + 2], acc2);
        acc3 = fma2(q3, M2[4 * jj + 3], acc3);
    }
    acc0 = add2(acc0, acc1);
    acc2 = add2(acc2, acc3);
    acc0 = add2(acc0, acc2);
    float lo, hi; unpackf2(acc0, lo, hi);
    return lo + hi;
}

// ---------------- one direction of the recursion ---------------------------
// FWD: alpha over s=1..M (M steps), broadcast value = alpha.
// BWD: beta from S-1 down to M ((S-1-M) steps), broadcast value v = pe_s*beta_s.
template <bool FWD>
__device__ __forceinline__ void run_dir(
    int b, int t, float* pbuf,
    const float* __restrict__ emis, const float* __restrict__ mask,
    const float* __restrict__ trans, const float* __restrict__ startT,
    const float* __restrict__ endT, float* __restrict__ out, int S)
{
    constexpr int T = 32;
    constexpr float LOG2E = 1.4426950408889634f;
    constexpr float LN2   = 0.6931471805599453f;
    constexpr int PF = 8;

    const long base = (long)b * S;
    const int M = (S - 1) / 2;
    const int NSTEP = FWD ? M : (S - 1 - M);

    // matrix for this lane, packed f32x2. FWD: column t; BWD: row t.
    unsigned long long M2[16];
    #pragma unroll
    for (int j = 0; j < 16; j++) {
        float lo = ex2f((FWD ? trans[(2 * j) * T + t]     : trans[t * T + 2 * j])     * LOG2E);
        float hi = ex2f((FWD ? trans[(2 * j + 1) * T + t] : trans[t * T + 2 * j + 1]) * LOG2E);
        M2[j] = packf2(lo, hi);
    }

    // init
    const float il  = FWD ? (startT[t] + emis[base * T + t]) : endT[t];
    const float al0 = il * LOG2E;
    float C = __shfl_sync(FULLMASK, al0, 0);
    float a = ex2f(al0 - C);                   // FWD: alpha. BWD: beta.
    float v = a;                               // BWD broadcast value
    if (!FWD) v = a * ex2f(emis[(base + S - 1) * T + t] * LOG2E);

    // RAW prefetch. FWD: pe&mask at pos 1+j. BWD: pe at pos S-2-j, mask at S-1-j.
    float rawe[PF], rawm[PF];
    #pragma unroll
    for (int k = 0; k < PF; k++) {
        rawe[k] = emis[(base + (FWD ? (1 + k) : (S - 2 - k))) * T + t];
        rawm[k] = mask[base + (FWD ? (1 + k) : (S - 1 - k))];
    }

    const uint32_t sbase = (uint32_t)__cvta_generic_to_shared(pbuf);

    auto step = [&](int j, int slot, bool do_prefetch, bool do_rescale) {
        const float pe = ex2f(rawe[slot] * LOG2E);   // hidden under broadcast
        const float mk = rawm[slot];
        if (do_prefetch) {
            int jn = j + PF; jn = (jn < NSTEP) ? jn : (NSTEP - 1);
            rawe[slot] = emis[(base + (FWD ? (1 + jn) : (S - 2 - jn))) * T + t];
            rawm[slot] = mask[base + (FWD ? (1 + jn) : (S - 1 - jn))];
        }

        float scale = 1.0f;
        if (do_rescale) {                 // every 4 steps, off-chain (shfl hidden)
            const float m0 = __shfl_sync(FULLMASK, FWD ? a : v, 0);
            unsigned ex = (__float_as_uint(m0) >> 23) & 0xFFu;
            ex = (ex < 1u) ? 1u : ((ex > 253u) ? 253u : ex);
            scale = __uint_as_float((254u - ex) << 23);      // 2^(127-ex)
            C += (float)((int)ex - 127);
        }
        const float mks  = mk * scale;               // off-chain
        const float bas  = (scale - mks) * a;        // (1-mk)*scale*a, off-chain

        const uint32_t off = sbase + ((j & 1) << 7);
        pbuf[((j & 1) << 5) + t] = FWD ? a : v;
        __syncthreads();                             // BAR @nw=1, drains STS

        const float ysum = matvec_dot(off, M2);

        if (FWD) {
            a = fmaf(mks * pe, ysum, bas);           // ONE chain FMA
        } else {
            v = fmaf(mks * pe, ysum, bas * pe);      // chain FMA (pe = next pos)
            a = fmaf(mks,      ysum, bas);           // beta, parallel FMA
        }
    };

    int j = 0;
    for (int blk = 0; blk < NSTEP / PF; blk++) {
        #pragma unroll
        for (int u = 0; u < PF; u++, j++) step(j, u, true, (u & 3) == 3);
    }
    const int rem = NSTEP % PF;
    #pragma unroll
    for (int u = 0; u < PF - 1; u++) {
        if (u < rem) { step(j, u, false, (u & 3) == 3); j++; }
    }

    g_vec[FWD ? 0 : 1][b][t] = a;
    if (t == 0) g_C[FWD ? 0 : 1][b] = C;

    // ---- combine: second finisher of the (fwd,bwd) pair does the dot ----
    __threadfence();
    int old = 0;
    if (t == 0) old = atomicAdd(&g_ticket[b], 1);
    old = __shfl_sync(FULLMASK, old, 0);
    if (old == 1) {
        __threadfence();                   // see the other direction's writes
        float p = g_vec[0][b][t] * g_vec[1][b][t];
        #pragma unroll
        for (int d = 16; d; d >>= 1) p += __shfl_xor_sync(FULLMASK, p, d);
        const float partition = (g_C[0][b] + g_C[1][b] + lg2f(p)) * LN2;
        if (t == 0) {
            atomicAdd(out, partition);
            g_ticket[b] = 0;               // reset for next graph replay
        }
    }
}

// ---------------- gold score path (independent of chains) ------------------
__device__ __forceinline__ void run_score(
    int b, int t,
    const float* __restrict__ emis, const int* __restrict__ tags32,
    const float* __restrict__ mask, const float* __restrict__ trans,
    const float* __restrict__ startT, const float* __restrict__ endT,
    float* __restrict__ out, int S)
{
    constexpr int T = 32;
    const long base = (long)b * S;

    // detect int64 vs int32 tag layout (little-endian)
    int nz = 0;
    for (int k = t; k < 128; k += 32) nz |= tags32[2 * k + 1];
    nz = __reduce_or_sync(FULLMASK, nz);
    const bool is64 = (nz == 0);

    float sc = 0.0f, msum = 0.0f;
    #pragma unroll 4
    for (int s = t; s < S; s += 32) {
        float mk = mask[base + s];
        msum += mk;
        if (s >= 1) {
            long ic = base + s, ip = base + s - 1;
            int tc = is64 ? tags32[2 * ic] : tags32[ic];
            int tp = is64 ? tags32[2 * ip] : tags32[ip];
            sc += (emis[ic * T + tc] + trans[tp * T + tc]) * mk;
        }
    }
    #pragma unroll
    for (int d = 16; d; d >>= 1) {
        sc   += __shfl_xor_sync(FULLMASK, sc, d);
        msum += __shfl_xor_sync(FULLMASK, msum, d);
    }

    if (t == 0) {
        const int last = (int)(msum + 0.5f) - 1;
        long i0 = base, il = base + last;
        int tg0 = is64 ? tags32[2 * i0] : tags32[i0];
        int tgl = is64 ? tags32[2 * il] : tags32[il];
        const float score = sc + startT[tg0] + emis[i0 * T + tg0] + endT[tgl];
        atomicAdd(out, -score);            // out accumulates -sum(score)
    }
}

// ---------------- fused launch: fwd | bwd | score --------------------------
__global__ void __launch_bounds__(32) crf_fused_kernel(
    const float* __restrict__ emis,
    const int*   __restrict__ tags32,
    const float* __restrict__ mask,
    const float* __restrict__ trans,
    const float* __restrict__ startT,
    const float* __restrict__ endT,
    float* __restrict__ out,
    int S, int B)
{
    __shared__ __align__(16) float pbuf[64];
    const int t = threadIdx.x;
    const int blk = blockIdx.x;

    if (blk < B) {
        run_dir<true >(blk, t, pbuf, emis, mask, trans, startT, endT, out, S);
    } else if (blk < 2 * B) {
        run_dir<false>(blk - B, t, pbuf, emis, mask, trans, startT, endT, out, S);
    } else {
        run_score(blk - 2 * B, t, emis, tags32, mask, trans, startT, endT, out, S);
    }
}

extern "C" void kernel_launch(void* const* d_in, const int* in_sizes, int n_in,
                              void* d_out, int out_size) {
    const float* emis   = (const float*)d_in[0];   // [B,S,T] float32
    const int*   tags   = (const int*)  d_in[1];   // [B,S] int (32/64 detected)
    const float* mask   = (const float*)d_in[2];   // [B,S] float32
    const float* trans  = (const float*)d_in[3];   // [T,T]
    const float* startT = (const float*)d_in[4];   // [T]
    const float* endT   = (const float*)d_in[5];   // [T]
    float* out = (float*)d_out;

    const int S  = 1024;
    const int BS = in_sizes[2];                    // mask element count = B*S
    const int B  = BS / S;

    cudaMemsetAsync(out, 0, sizeof(float));        // memset graph node, no kernel
    crf_fused_kernel<<<3 * B, 32>>>(emis, tags, mask, trans, startT, endT, out, S, B);
}

// round 13
// speedup vs baseline: 1.4165x; 1.4165x over previous
#include <cuda_runtime.h>
#include <cstdint>

// CRF negative log-likelihood on GB300 (sm_103a).
// B=512, S=1024, T=32. Forward/backward split at m=(S-1)/2:
//   Z = sum_t alpha_t(m) * beta_t(m).
// ONE fused launch, grid=3B: [0,B) fwd chains, [B,2B) bwd chains, [2B,3B)
// gold-score blocks; tiny combine kernel after (kernel boundary = ordering).
// R13: removed __threadfence ticket (gpu-scope fence emits CCTL.IVALL -> L1
// flush per CTA, regressed R12); prefetch is clamp-free + strength-reduced
// (pure pointer increments, positions always in-bounds); step counts are
// compile-time (S=1024). Chain core unchanged: SMEM broadcast (STS+BAR@nw=1+
// 8x LDS.128 volatile), 16x FFMA2 with preloaded exp(trans), raw prefetch
// (PF=8) converted at consumption, rescale every 4 steps off-chain, ONE
// serial-chain FMA per step.

#define FULLMASK 0xFFFFFFFFu
#define SFIX 1024                      // problem shape is fixed

__device__ float g_vec[2][2048][32];   // [dir][seq][tag] boundary vectors
__device__ float g_C[2][2048];         // [dir][seq] log2 offsets

__device__ __forceinline__ float ex2f(float x) {
    float r; asm("ex2.approx.ftz.f32 %0, %1;" : "=f"(r) : "f"(x)); return r;
}
__device__ __forceinline__ float lg2f(float x) {
    float r; asm("lg2.approx.ftz.f32 %0, %1;" : "=f"(r) : "f"(x)); return r;
}
__device__ __forceinline__ unsigned long long packf2(float lo, float hi) {
    unsigned long long d; asm("mov.b64 %0, {%1, %2};" : "=l"(d) : "f"(lo), "f"(hi)); return d;
}
__device__ __forceinline__ void unpackf2(unsigned long long d, float& lo, float& hi) {
    asm("mov.b64 {%0, %1}, %2;" : "=f"(lo), "=f"(hi) : "l"(d));
}
__device__ __forceinline__ unsigned long long fma2(unsigned long long a,
                                                   unsigned long long b,
                                                   unsigned long long c) {
    unsigned long long d;
    asm("fma.rn.f32x2 %0, %1, %2, %3;" : "=l"(d) : "l"(a), "l"(b), "l"(c));
    return d;
}
__device__ __forceinline__ unsigned long long add2(unsigned long long a,
                                                   unsigned long long b) {
    unsigned long long d;
    asm("add.rn.f32x2 %0, %1, %2;" : "=l"(d) : "l"(a), "l"(b));
    return d;
}

// dot of broadcast slab with this lane's matrix pairs: 8x LDS.128 + 16x FFMA2
__device__ __forceinline__ float matvec_dot(uint32_t off, const unsigned long long* M2) {
    unsigned long long acc0 = 0ull, acc1 = 0ull, acc2 = 0ull, acc3 = 0ull;
    #pragma unroll
    for (int jj = 0; jj < 4; jj++) {
        unsigned long long q0, q1, q2, q3;
        asm volatile("ld.shared.v2.u64 {%0, %1}, [%2];"
            : "=l"(q0), "=l"(q1) : "r"(off + 32u * jj) : "memory");
        asm volatile("ld.shared.v2.u64 {%0, %1}, [%2 + 16];"
            : "=l"(q2), "=l"(q3) : "r"(off + 32u * jj) : "memory");
        acc0 = fma2(q0, M2[4 * jj + 0], acc0);
        acc1 = fma2(q1, M2[4 * jj + 1], acc1);
        acc2 = fma2(q2, M2[4 * jj + 2], acc2);
        acc3 = fma2(q3, M2[4 * jj + 3], acc3);
    }
    acc0 = add2(acc0, acc1);
    acc2 = add2(acc2, acc3);
    acc0 = add2(acc0, acc2);
    float lo, hi; unpackf2(acc0, lo, hi);
    return lo + hi;
}

// ---------------- one direction of the recursion ---------------------------
// FWD: alpha over s=1..M (M steps), broadcast value = alpha.
// BWD: beta from S-1 down to M (S-1-M steps), broadcast value v = pe_s*beta_s.
template <bool FWD>
__device__ __forceinline__ void run_dir(
    int b, int t, float* pbuf,
    const float* __restrict__ emis, const float* __restrict__ mask,
    const float* __restrict__ trans, const float* __restrict__ startT,
    const float* __restrict__ endT)
{
    constexpr int T = 32;
    constexpr int S = SFIX;
    constexpr float LOG2E = 1.4426950408889634f;
    constexpr int PF = 8;
    constexpr int M = (S - 1) / 2;             // 511
    constexpr int NSTEP = FWD ? M : (S - 1 - M);   // 511 / 512
    constexpr int NBLK = NSTEP / PF;           // 63 / 64
    constexpr int NREM = NSTEP % PF;           // 7 / 0

    const long base = (long)b * S;

    // matrix for this lane, packed f32x2. FWD: column t; BWD: row t.
    unsigned long long M2[16];
    #pragma unroll
    for (int j = 0; j < 16; j++) {
        float lo = ex2f((FWD ? trans[(2 * j) * T + t]     : trans[t * T + 2 * j])     * LOG2E);
        float hi = ex2f((FWD ? trans[(2 * j + 1) * T + t] : trans[t * T + 2 * j + 1]) * LOG2E);
        M2[j] = packf2(lo, hi);
    }

    // init
    const float il  = FWD ? (startT[t] + emis[base * T + t]) : endT[t];
    const float al0 = il * LOG2E;
    float C = __shfl_sync(FULLMASK, al0, 0);
    float a = ex2f(al0 - C);                   // FWD: alpha. BWD: beta.
    float v = a;                               // BWD broadcast value
    if (!FWD) v = a * ex2f(emis[(base + S - 1) * T + t] * LOG2E);

    // RAW prefetch. FWD: pe&mask at pos 1+k. BWD: pe at S-2-k, mask at S-1-k.
    float rawe[PF], rawm[PF];
    #pragma unroll
    for (int k = 0; k < PF; k++) {
        rawe[k] = emis[(base + (FWD ? (1 + k) : (S - 2 - k))) * T + t];
        rawm[k] = mask[base + (FWD ? (1 + k) : (S - 1 - k))];
    }
    // Strength-reduced prefetch pointers (position of step j+PF at step j).
    // Clamp-free: max FWD pos = NSTEP+PF < S-1; min BWD pos = M-PF >= 0.
    const float* pe_pf = emis + (base + (FWD ? (1 + PF) : (S - 2 - PF))) * T + t;
    const float* pm_pf = mask + base + (FWD ? (1 + PF) : (S - 1 - PF));

    const uint32_t sbase = (uint32_t)__cvta_generic_to_shared(pbuf);

    auto step = [&](int j, int slot, bool do_rescale) {
        const float pe = ex2f(rawe[slot] * LOG2E);   // hidden under broadcast
        const float mk = rawm[slot];
        rawe[slot] = *pe_pf;  pe_pf += FWD ? T : -T; // consumed PF steps later
        rawm[slot] = *pm_pf;  pm_pf += FWD ? 1 : -1;

        float scale = 1.0f;
        if (do_rescale) {                 // every 4 steps, off-chain (shfl hidden)
            const float m0 = __shfl_sync(FULLMASK, FWD ? a : v, 0);
            unsigned ex = (__float_as_uint(m0) >> 23) & 0xFFu;
            ex = (ex < 1u) ? 1u : ((ex > 253u) ? 253u : ex);
            scale = __uint_as_float((254u - ex) << 23);      // 2^(127-ex)
            C += (float)((int)ex - 127);
        }
        const float mks = mk * scale;                // off-chain
        const float bas = (scale - mks) * a;         // (1-mk)*scale*a, off-chain

        const uint32_t off = sbase + ((j & 1) << 7);
        pbuf[((j & 1) << 5) + t] = FWD ? a : v;
        __syncthreads();                             // BAR @nw=1, drains STS

        const float ysum = matvec_dot(off, M2);

        if (FWD) {
            a = fmaf(mks * pe, ysum, bas);           // ONE chain FMA
        } else {
            v = fmaf(mks * pe, ysum, bas * pe);      // chain FMA (pe = next pos)
            a = fmaf(mks,      ysum, bas);           // beta, parallel FMA
        }
    };

    int j = 0;
    for (int blk = 0; blk < NBLK; blk++) {
        #pragma unroll
        for (int u = 0; u < PF; u++, j++) step(j, u, (u & 3) == 3);
    }
    #pragma unroll
    for (int u = 0; u < NREM; u++, j++) step(j, u, (u & 3) == 3);

    g_vec[FWD ? 0 : 1][b][t] = a;
    if (t == 0) g_C[FWD ? 0 : 1][b] = C;
}

// ---------------- gold score path (independent of chains) ------------------
__device__ __forceinline__ void run_score(
    int b, int t,
    const float* __restrict__ emis, const int* __restrict__ tags32,
    const float* __restrict__ mask, const float* __restrict__ trans,
    const float* __restrict__ startT, const float* __restrict__ endT,
    float* __restrict__ out)
{
    constexpr int T = 32;
    constexpr int S = SFIX;
    const long base = (long)b * S;

    // detect int64 vs int32 tag layout (little-endian)
    int nz = 0;
    for (int k = t; k < 128; k += 32) nz |= tags32[2 * k + 1];
    nz = __reduce_or_sync(FULLMASK, nz);
    const bool is64 = (nz == 0);

    float sc = 0.0f, msum = 0.0f;
    #pragma unroll 4
    for (int s = t; s < S; s += 32) {
        float mk = mask[base + s];
        msum += mk;
        if (s >= 1) {
            long ic = base + s, ip = base + s - 1;
            int tc = is64 ? tags32[2 * ic] : tags32[ic];
            int tp = is64 ? tags32[2 * ip] : tags32[ip];
            sc += (emis[ic * T + tc] + trans[tp * T + tc]) * mk;
        }
    }
    #pragma unroll
    for (int d = 16; d; d >>= 1) {
        sc   += __shfl_xor_sync(FULLMASK, sc, d);
        msum += __shfl_xor_sync(FULLMASK, msum, d);
    }

    if (t == 0) {
        const int last = (int)(msum + 0.5f) - 1;
        long i0 = base, il = base + last;
        int tg0 = is64 ? tags32[2 * i0] : tags32[i0];
        int tgl = is64 ? tags32[2 * il] : tags32[il];
        const float score = sc + startT[tg0] + emis[i0 * T + tg0] + endT[tgl];
        atomicAdd(out, -score);            // out accumulates -sum(score)
    }
}

// ---------------- fused launch: fwd | bwd | score --------------------------
__global__ void __launch_bounds__(32) crf_fused_kernel(
    const float* __restrict__ emis,
    const int*   __restrict__ tags32,
    const float* __restrict__ mask,
    const float* __restrict__ trans,
    const float* __restrict__ startT,
    const float* __restrict__ endT,
    float* __restrict__ out,
    int B)
{
    __shared__ __align__(16) float pbuf[64];
    const int t = threadIdx.x;
    const int blk = blockIdx.x;

    if (blk < B) {
        run_dir<true >(blk, t, pbuf, emis, mask, trans, startT, endT);
    } else if (blk < 2 * B) {
        run_dir<false>(blk - B, t, pbuf, emis, mask, trans, startT, endT);
    } else {
        run_score(blk - 2 * B, t, emis, tags32, mask, trans, startT, endT, out);
    }
}

// ---------------- combine: alpha.beta dot -> partition ---------------------
__global__ void __launch_bounds__(32) crf_combine_kernel(float* __restrict__ out)
{
    constexpr float LN2 = 0.6931471805599453f;
    const int b = blockIdx.x;
    const int t = threadIdx.x;

    float p = g_vec[0][b][t] * g_vec[1][b][t];
    #pragma unroll
    for (int d = 16; d; d >>= 1) p += __shfl_xor_sync(FULLMASK, p, d);
    const float partition = (g_C[0][b] + g_C[1][b] + lg2f(p)) * LN2;

    if (t == 0) atomicAdd(out, partition);
}

extern "C" void kernel_launch(void* const* d_in, const int* in_sizes, int n_in,
                              void* d_out, int out_size) {
    const float* emis   = (const float*)d_in[0];   // [B,S,T] float32
    const int*   tags   = (const int*)  d_in[1];   // [B,S] int (32/64 detected)
    const float* mask   = (const float*)d_in[2];   // [B,S] float32
    const float* trans  = (const float*)d_in[3];   // [T,T]
    const float* startT = (const float*)d_in[4];   // [T]
    const float* endT   = (const float*)d_in[5];   // [T]
    float* out = (float*)d_out;

    const int B = in_sizes[2] / SFIX;              // mask elements = B*S

    cudaMemsetAsync(out, 0, sizeof(float));        // memset node, no kernel
    crf_fused_kernel<<<3 * B, 32>>>(emis, tags, mask, trans, startT, endT, out, B);
    crf_combine_kernel<<<B, 32>>>(out);
}